// round 2
// baseline (speedup 1.0000x reference)
#include <cuda_runtime.h>

#define Bb 8
#define Tt 2048
#define Cc 1024
#define Hh 64
#define BT (Bb*Tt)

// scratch for projected q,k,v — __device__ globals per allocation rules
__device__ float g_q[BT*Hh];
__device__ float g_k[BT*Hh];
__device__ float g_v[BT*Hh];

__device__ __forceinline__ float fast_exp2(float x){
    float y;
    asm("ex2.approx.ftz.f32 %0, %1;" : "=f"(y) : "f"(x));
    return y;
}

// ---------------------------------------------------------------------------
// Projection: out[BT x 64] = x[BT x 1024] @ W[1024 x 64], one of 3 per blockIdx.y
// 128x64 tile per block, 256 threads, 4x8 register tile per thread.
// ---------------------------------------------------------------------------
__global__ __launch_bounds__(256) void proj_kernel(
    const float* __restrict__ x,
    const float* __restrict__ Wk,
    const float* __restrict__ Wq,
    const float* __restrict__ Wv)
{
    const int m = blockIdx.y;
    const float* __restrict__ W = (m == 0) ? Wk : (m == 1) ? Wq : Wv;
    float* __restrict__ out = (m == 0) ? g_k : (m == 1) ? g_q : g_v;

    const int row0 = blockIdx.x * 128;
    const int tid = threadIdx.x;
    const int tr = tid >> 3;       // 0..31 -> rows tr + 32*i
    const int tc = tid & 7;        // 0..7  -> cols tc*8 .. tc*8+7

    __shared__ float xs[128][17];  // row-major, pad 17: a-loads conflict-free
    __shared__ float ws[16][72];   // pad 72 (288B): float4-aligned rows

    float acc[4][8];
#pragma unroll
    for (int i = 0; i < 4; i++)
#pragma unroll
        for (int j = 0; j < 8; j++) acc[i][j] = 0.f;

    for (int kc = 0; kc < Cc; kc += 16) {
        // x chunk: 128x16 = 512 float4, 2 per thread
#pragma unroll
        for (int u = 0; u < 2; u++) {
            int f  = tid + 256 * u;
            int rr = f >> 2;
            int cc = (f & 3) * 4;
            float4 v = *(const float4*)&x[(size_t)(row0 + rr) * Cc + kc + cc];
            xs[rr][cc + 0] = v.x; xs[rr][cc + 1] = v.y;
            xs[rr][cc + 2] = v.z; xs[rr][cc + 3] = v.w;
        }
        // W chunk: 16x64 = 256 float4, 1 per thread
        {
            int rr = tid >> 4;
            int cc = (tid & 15) * 4;
            *(float4*)&ws[rr][cc] = *(const float4*)&W[(size_t)(kc + rr) * Hh + cc];
        }
        __syncthreads();
#pragma unroll
        for (int k = 0; k < 16; k++) {
            float a[4];
#pragma unroll
            for (int i = 0; i < 4; i++) a[i] = xs[tr + 32 * i][k];
            float4 b0 = *(const float4*)&ws[k][tc * 8];
            float4 b1 = *(const float4*)&ws[k][tc * 8 + 4];
#pragma unroll
            for (int i = 0; i < 4; i++) {
                acc[i][0] += a[i] * b0.x; acc[i][1] += a[i] * b0.y;
                acc[i][2] += a[i] * b0.z; acc[i][3] += a[i] * b0.w;
                acc[i][4] += a[i] * b1.x; acc[i][5] += a[i] * b1.y;
                acc[i][6] += a[i] * b1.z; acc[i][7] += a[i] * b1.w;
            }
        }
        __syncthreads();
    }
#pragma unroll
    for (int i = 0; i < 4; i++) {
        size_t row = row0 + tr + 32 * i;
        float4 v0 = make_float4(acc[i][0], acc[i][1], acc[i][2], acc[i][3]);
        float4 v1 = make_float4(acc[i][4], acc[i][5], acc[i][6], acc[i][7]);
        *(float4*)&out[row * Hh + tc * 8 + 0] = v0;
        *(float4*)&out[row * Hh + tc * 8 + 4] = v1;
    }
}

// ---------------------------------------------------------------------------
// Flash attention: BM=32 rows, BN=64 keys, 128 threads (4 threads/row, 16 dims).
// Chunked online softmax (16 keys/chunk), scores in registers, no S smem.
// grid (T/32, B), heavy tiles launched first.
// ---------------------------------------------------------------------------
__global__ __launch_bounds__(128) void attn_kernel(float* __restrict__ out)
{
    const int b    = blockIdx.y;
    const int qi   = gridDim.x - 1 - blockIdx.x;   // heavy tiles first
    const int q0   = qi * 32;
    const int tid  = threadIdx.x;
    const int r    = tid >> 2;      // query row in tile: 0..31
    const int doff = (tid & 3) * 16;

    __shared__ float Ks[64 * 64];
    __shared__ float Vs[64 * 64];

    // softmax scale (1/sqrt(64)) folded with log2(e)
    const float scale = 0.125f * 1.44269504088896340736f;

    float q[16];
    {
        const float* qp = &g_q[((size_t)b * Tt + q0 + r) * Hh + doff];
#pragma unroll
        for (int d4 = 0; d4 < 4; d4++) {
            float4 v = *(const float4*)&qp[d4 * 4];
            q[d4 * 4 + 0] = v.x; q[d4 * 4 + 1] = v.y;
            q[d4 * 4 + 2] = v.z; q[d4 * 4 + 3] = v.w;
        }
    }
    float acc[16];
#pragma unroll
    for (int d = 0; d < 16; d++) acc[d] = 0.f;
    float m = -1e30f, l = 0.f;

    for (int n0 = 0; n0 <= q0; n0 += 64) {
        __syncthreads();
        {
            const float4* kp = (const float4*)&g_k[((size_t)b * Tt + n0) * Hh];
            const float4* vp = (const float4*)&g_v[((size_t)b * Tt + n0) * Hh];
#pragma unroll
            for (int u = 0; u < 8; u++) {
                int f = tid + 128 * u;        // 1024 float4 per tile
                ((float4*)Ks)[f] = kp[f];
                ((float4*)Vs)[f] = vp[f];
            }
        }
        __syncthreads();

#pragma unroll
        for (int c = 0; c < 4; c++) {
            float sreg[16];
            float cmax = -1e30f;
#pragma unroll
            for (int jj = 0; jj < 16; jj++) {
                int j = c * 16 + jj;
                const float* kr = &Ks[j * 64 + doff];
                float p0 = 0.f, p1 = 0.f, p2 = 0.f, p3 = 0.f;
#pragma unroll
                for (int d4 = 0; d4 < 4; d4++) {
                    float4 kv = *(const float4*)&kr[d4 * 4];
                    p0 += q[d4 * 4 + 0] * kv.x;
                    p1 += q[d4 * 4 + 1] * kv.y;
                    p2 += q[d4 * 4 + 2] * kv.z;
                    p3 += q[d4 * 4 + 3] * kv.w;
                }
                float s = (p0 + p1) + (p2 + p3);
                s += __shfl_xor_sync(0xffffffffu, s, 1);
                s += __shfl_xor_sync(0xffffffffu, s, 2);
                s *= scale;
                if (n0 + j > q0 + r) s = -1e30f;       // causal mask
                sreg[jj] = s;
                cmax = fmaxf(cmax, s);
            }
            float m_new = fmaxf(m, cmax);
            float corr  = fast_exp2(m - m_new);
            l *= corr;
#pragma unroll
            for (int d = 0; d < 16; d++) acc[d] *= corr;

#pragma unroll
            for (int jj = 0; jj < 16; jj++) {
                int j = c * 16 + jj;
                float p = fast_exp2(sreg[jj] - m_new);
                l += p;
                const float* vr = &Vs[j * 64 + doff];
#pragma unroll
                for (int d4 = 0; d4 < 4; d4++) {
                    float4 vv = *(const float4*)&vr[d4 * 4];
                    acc[d4 * 4 + 0] += p * vv.x;
                    acc[d4 * 4 + 1] += p * vv.y;
                    acc[d4 * 4 + 2] += p * vv.z;
                    acc[d4 * 4 + 3] += p * vv.w;
                }
            }
            m = m_new;
        }
    }

    const float inv = 1.0f / l;
    float* op = &out[((size_t)b * Tt + q0 + r) * Hh + doff];
#pragma unroll
    for (int d4 = 0; d4 < 4; d4++) {
        float4 v;
        v.x = acc[d4 * 4 + 0] * inv;
        v.y = acc[d4 * 4 + 1] * inv;
        v.z = acc[d4 * 4 + 2] * inv;
        v.w = acc[d4 * 4 + 3] * inv;
        *(float4*)&op[d4 * 4] = v;
    }
}

extern "C" void kernel_launch(void* const* d_in, const int* in_sizes, int n_in,
                              void* d_out, int out_size)
{
    const float* x  = (const float*)d_in[0];
    const float* Wk = (const float*)d_in[1];
    const float* Wq = (const float*)d_in[2];
    const float* Wv = (const float*)d_in[3];
    float* out = (float*)d_out;

    dim3 pg(BT / 128, 3);
    proj_kernel<<<pg, 256>>>(x, Wk, Wq, Wv);

    dim3 ag(Tt / 32, Bb);
    attn_kernel<<<ag, 128>>>(out);
}

// round 3
// speedup vs baseline: 6.5189x; 6.5189x over previous
#include <cuda_runtime.h>

#define Bb 8
#define Tt 2048
#define Cc 1024
#define Hh 64
#define BT (Bb*Tt)

// scratch for projected q,k,v — __device__ globals per allocation rules
__device__ float g_q[BT*Hh];
__device__ float g_k[BT*Hh];
__device__ float g_v[BT*Hh];

__device__ __forceinline__ float fast_exp2(float x){
    float y;
    asm("ex2.approx.ftz.f32 %0, %1;" : "=f"(y) : "f"(x));
    return y;
}
__device__ __forceinline__ unsigned f2tf(float f){
    unsigned r;
    asm("cvt.rna.tf32.f32 %0, %1;" : "=r"(r) : "f"(f));
    return r;
}
__device__ __forceinline__ void mma_tf32(float c[4], const unsigned a[4], const unsigned b[2]){
    asm volatile("mma.sync.aligned.m16n8k8.row.col.f32.tf32.tf32.f32 "
        "{%0,%1,%2,%3}, {%4,%5,%6,%7}, {%8,%9}, {%0,%1,%2,%3};"
        : "+f"(c[0]), "+f"(c[1]), "+f"(c[2]), "+f"(c[3])
        : "r"(a[0]), "r"(a[1]), "r"(a[2]), "r"(a[3]), "r"(b[0]), "r"(b[1]));
}

// ---------------------------------------------------------------------------
// Projection: out[BT x 64] = x[BT x 1024] @ W[1024 x 64]  (tf32 mma)
// 128x64 tile per block, 128 threads (4 warps), warp = 32 rows (2 m-frags x 8 n-frags)
// ---------------------------------------------------------------------------
__global__ __launch_bounds__(128) void proj_kernel(
    const float* __restrict__ x,
    const float* __restrict__ Wk,
    const float* __restrict__ Wq,
    const float* __restrict__ Wv)
{
    const int m = blockIdx.y;
    const float* __restrict__ W = (m == 0) ? Wk : (m == 1) ? Wq : Wv;
    float* __restrict__ out = (m == 0) ? g_k : (m == 1) ? g_q : g_v;

    const int row0 = blockIdx.x * 128;
    const int tid  = threadIdx.x;
    const int warp = tid >> 5;
    const int lane = tid & 31;
    const int g = lane >> 2;   // group id 0..7
    const int t = lane & 3;    // thread-in-group

    // strides: 36 ≡ 4 (mod 32) and 68 ≡ 4 (mod 32) -> frag LDS conflict-free
    __shared__ unsigned xs[128][36];   // x chunk as tf32
    __shared__ unsigned ws[32][68];    // W chunk as tf32

    float c[2][8][4];
#pragma unroll
    for (int mf = 0; mf < 2; mf++)
#pragma unroll
        for (int nf = 0; nf < 8; nf++)
#pragma unroll
            for (int i = 0; i < 4; i++) c[mf][nf][i] = 0.f;

    for (int kc = 0; kc < Cc; kc += 32) {
        // load x chunk 128x32 (1024 float4, 8/thread), convert to tf32
#pragma unroll
        for (int u = 0; u < 8; u++) {
            int f  = tid + 128 * u;
            int rr = f >> 3;
            int c4 = (f & 7) * 4;
            float4 v = *(const float4*)&x[(size_t)(row0 + rr) * Cc + kc + c4];
            *(uint4*)&xs[rr][c4] = make_uint4(f2tf(v.x), f2tf(v.y), f2tf(v.z), f2tf(v.w));
        }
        // load W chunk 32x64 (512 float4, 4/thread)
#pragma unroll
        for (int u = 0; u < 4; u++) {
            int f  = tid + 128 * u;
            int rr = f >> 4;
            int c4 = (f & 15) * 4;
            float4 v = *(const float4*)&W[(size_t)(kc + rr) * Hh + c4];
            *(uint4*)&ws[rr][c4] = make_uint4(f2tf(v.x), f2tf(v.y), f2tf(v.z), f2tf(v.w));
        }
        __syncthreads();
#pragma unroll
        for (int ks = 0; ks < 4; ks++) {
            const int k0 = ks * 8;
            unsigned b[8][2];
#pragma unroll
            for (int nf = 0; nf < 8; nf++) {
                b[nf][0] = ws[k0 + t][nf * 8 + g];
                b[nf][1] = ws[k0 + t + 4][nf * 8 + g];
            }
#pragma unroll
            for (int mf = 0; mf < 2; mf++) {
                const int rg = warp * 32 + mf * 16 + g;
                unsigned a[4] = { xs[rg][k0 + t], xs[rg + 8][k0 + t],
                                  xs[rg][k0 + t + 4], xs[rg + 8][k0 + t + 4] };
#pragma unroll
                for (int nf = 0; nf < 8; nf++) mma_tf32(c[mf][nf], a, b[nf]);
            }
        }
        __syncthreads();
    }
#pragma unroll
    for (int mf = 0; mf < 2; mf++) {
        const int rg = row0 + warp * 32 + mf * 16 + g;
#pragma unroll
        for (int nf = 0; nf < 8; nf++) {
            const int col = nf * 8 + 2 * t;
            *(float2*)&out[(size_t)rg * Hh + col]       = make_float2(c[mf][nf][0], c[mf][nf][1]);
            *(float2*)&out[(size_t)(rg + 8) * Hh + col] = make_float2(c[mf][nf][2], c[mf][nf][3]);
        }
    }
}

// ---------------------------------------------------------------------------
// Flash attention, tf32 mma. 256 threads = 2 groups x 4 warps.
// Group 0 -> q-tile p, group 1 -> q-tile (T/64-1-p): balanced causal pairing.
// Each warp: 16 query rows x 64 keys (S) and x 64 dims (O).
// ---------------------------------------------------------------------------
__global__ __launch_bounds__(256) void attn_kernel(float* __restrict__ out)
{
    const int b    = blockIdx.y;
    const int pair = blockIdx.x;              // 0..15
    const int tid  = threadIdx.x;
    const int warp = tid >> 5;
    const int lane = tid & 31;
    const int group = warp >> 2;              // 0 or 1
    const int qt   = (group == 0) ? pair : (Tt / 64 - 1 - pair);
    const int q0   = qt * 64;
    const int wr0  = (warp & 3) * 16;         // warp's row slice in tile
    const int g = lane >> 2;
    const int t = lane & 3;
    const int wtid = tid & 127;               // thread id within group

    extern __shared__ unsigned sm[];
    unsigned* Ks = sm + group * (2 * 64 * 68);
    unsigned* Vs = Ks + 64 * 68;

    const float scale = 0.125f * 1.44269504088896340736f;  // 1/sqrt(64) * log2(e)

    // Q A-frags (scale folded, tf32), held in registers for entire kernel
    unsigned qa[8][4];
    {
        const float* qp = g_q + ((size_t)b * Tt + q0 + wr0) * Hh;
#pragma unroll
        for (int kc = 0; kc < 8; kc++) {
            qa[kc][0] = f2tf(qp[g * Hh + kc * 8 + t] * scale);
            qa[kc][1] = f2tf(qp[(g + 8) * Hh + kc * 8 + t] * scale);
            qa[kc][2] = f2tf(qp[g * Hh + kc * 8 + t + 4] * scale);
            qa[kc][3] = f2tf(qp[(g + 8) * Hh + kc * 8 + t + 4] * scale);
        }
    }

    float oc[8][4];
#pragma unroll
    for (int nf = 0; nf < 8; nf++)
#pragma unroll
        for (int i = 0; i < 4; i++) oc[nf][i] = 0.f;
    float m0 = -1e30f, m1 = -1e30f, l0 = 0.f, l1 = 0.f;

    const int src0 = (lane & ~3) | (t >> 1);
    const int src2 = src0 + 2;

    for (int n0 = 0; n0 <= q0; n0 += 64) {
        asm volatile("bar.sync %0, 128;" :: "r"(group + 1));
        {
            const float4* kp = (const float4*)(g_k + ((size_t)b * Tt + n0) * Hh);
            const float4* vp = (const float4*)(g_v + ((size_t)b * Tt + n0) * Hh);
#pragma unroll
            for (int u = 0; u < 8; u++) {
                int f   = wtid + 128 * u;     // 0..1023 float4 of the 64x64 tile
                int row = f >> 4;
                int c4  = (f & 15) * 4;
                float4 kv = kp[f];
                *(uint4*)&Ks[row * 68 + c4] = make_uint4(f2tf(kv.x), f2tf(kv.y), f2tf(kv.z), f2tf(kv.w));
                float4 vv = vp[f];
                *(uint4*)&Vs[row * 68 + c4] = make_uint4(f2tf(vv.x), f2tf(vv.y), f2tf(vv.z), f2tf(vv.w));
            }
        }
        asm volatile("bar.sync %0, 128;" :: "r"(group + 1));

        // S = Q K^T  (already in log2 domain via folded scale)
        float sc_[8][4];
#pragma unroll
        for (int nf = 0; nf < 8; nf++)
#pragma unroll
            for (int i = 0; i < 4; i++) sc_[nf][i] = 0.f;
#pragma unroll
        for (int kc = 0; kc < 8; kc++) {
#pragma unroll
            for (int nf = 0; nf < 8; nf++) {
                unsigned bk[2] = { Ks[(nf * 8 + g) * 68 + kc * 8 + t],
                                   Ks[(nf * 8 + g) * 68 + kc * 8 + t + 4] };
                mma_tf32(sc_[nf], qa[kc], bk);
            }
        }

        // causal mask (only diagonal tile)
        if (n0 == q0) {
#pragma unroll
            for (int nf = 0; nf < 8; nf++) {
                const int kl = nf * 8 + 2 * t;
                if (kl     > wr0 + g)     sc_[nf][0] = -1e30f;
                if (kl + 1 > wr0 + g)     sc_[nf][1] = -1e30f;
                if (kl     > wr0 + g + 8) sc_[nf][2] = -1e30f;
                if (kl + 1 > wr0 + g + 8) sc_[nf][3] = -1e30f;
            }
        }

        // online softmax (rows g and g+8 of this warp's 16-row slice)
        float mx0 = -1e30f, mx1 = -1e30f;
#pragma unroll
        for (int nf = 0; nf < 8; nf++) {
            mx0 = fmaxf(mx0, fmaxf(sc_[nf][0], sc_[nf][1]));
            mx1 = fmaxf(mx1, fmaxf(sc_[nf][2], sc_[nf][3]));
        }
        mx0 = fmaxf(mx0, __shfl_xor_sync(0xffffffffu, mx0, 1));
        mx0 = fmaxf(mx0, __shfl_xor_sync(0xffffffffu, mx0, 2));
        mx1 = fmaxf(mx1, __shfl_xor_sync(0xffffffffu, mx1, 1));
        mx1 = fmaxf(mx1, __shfl_xor_sync(0xffffffffu, mx1, 2));

        const float m0n = fmaxf(m0, mx0);
        const float m1n = fmaxf(m1, mx1);
        const float corr0 = fast_exp2(m0 - m0n);
        const float corr1 = fast_exp2(m1 - m1n);
        l0 *= corr0; l1 *= corr1;
#pragma unroll
        for (int nf = 0; nf < 8; nf++) {
            oc[nf][0] *= corr0; oc[nf][1] *= corr0;
            oc[nf][2] *= corr1; oc[nf][3] *= corr1;
        }
        unsigned pu[8][4];
#pragma unroll
        for (int nf = 0; nf < 8; nf++) {
            float p0 = fast_exp2(sc_[nf][0] - m0n);
            float p1 = fast_exp2(sc_[nf][1] - m0n);
            float p2 = fast_exp2(sc_[nf][2] - m1n);
            float p3 = fast_exp2(sc_[nf][3] - m1n);
            l0 += p0 + p1;
            l1 += p2 + p3;
            pu[nf][0] = f2tf(p0); pu[nf][1] = f2tf(p1);
            pu[nf][2] = f2tf(p2); pu[nf][3] = f2tf(p3);
        }
        m0 = m0n; m1 = m1n;

        // O += P V : re-layout P frags C->A via intra-group shuffles
#pragma unroll
        for (int kc = 0; kc < 8; kc++) {
            unsigned a[4];
            {
                unsigned e0 = __shfl_sync(0xffffffffu, pu[kc][0], src0);
                unsigned o0 = __shfl_sync(0xffffffffu, pu[kc][1], src0);
                a[0] = (t & 1) ? o0 : e0;
                unsigned e1 = __shfl_sync(0xffffffffu, pu[kc][2], src0);
                unsigned o1 = __shfl_sync(0xffffffffu, pu[kc][3], src0);
                a[1] = (t & 1) ? o1 : e1;
                unsigned e2 = __shfl_sync(0xffffffffu, pu[kc][0], src2);
                unsigned o2 = __shfl_sync(0xffffffffu, pu[kc][1], src2);
                a[2] = (t & 1) ? o2 : e2;
                unsigned e3 = __shfl_sync(0xffffffffu, pu[kc][2], src2);
                unsigned o3 = __shfl_sync(0xffffffffu, pu[kc][3], src2);
                a[3] = (t & 1) ? o3 : e3;
            }
#pragma unroll
            for (int nf = 0; nf < 8; nf++) {
                unsigned bv[2] = { Vs[(kc * 8 + t) * 68 + nf * 8 + g],
                                   Vs[(kc * 8 + t + 4) * 68 + nf * 8 + g] };
                mma_tf32(oc[nf], a, bv);
            }
        }
    }

    // finalize
    l0 += __shfl_xor_sync(0xffffffffu, l0, 1);
    l0 += __shfl_xor_sync(0xffffffffu, l0, 2);
    l1 += __shfl_xor_sync(0xffffffffu, l1, 1);
    l1 += __shfl_xor_sync(0xffffffffu, l1, 2);
    const float inv0 = 1.0f / l0;
    const float inv1 = 1.0f / l1;

    const int rg = q0 + wr0 + g;
#pragma unroll
    for (int nf = 0; nf < 8; nf++) {
        const int col = nf * 8 + 2 * t;
        *(float2*)&out[((size_t)b * Tt + rg) * Hh + col] =
            make_float2(oc[nf][0] * inv0, oc[nf][1] * inv0);
        *(float2*)&out[((size_t)b * Tt + rg + 8) * Hh + col] =
            make_float2(oc[nf][2] * inv1, oc[nf][3] * inv1);
    }
}

extern "C" void kernel_launch(void* const* d_in, const int* in_sizes, int n_in,
                              void* d_out, int out_size)
{
    const float* x  = (const float*)d_in[0];
    const float* Wk = (const float*)d_in[1];
    const float* Wq = (const float*)d_in[2];
    const float* Wv = (const float*)d_in[3];
    float* out = (float*)d_out;

    dim3 pg(BT / 128, 3);
    proj_kernel<<<pg, 128>>>(x, Wk, Wq, Wv);

    static const int attn_smem = 2 * 2 * 64 * 68 * 4;  // 69632 B
    cudaFuncSetAttribute(attn_kernel, cudaFuncAttributeMaxDynamicSharedMemorySize, attn_smem);
    dim3 ag(Tt / 64 / 2, Bb);
    attn_kernel<<<ag, 256, attn_smem>>>(out);
}

// round 4
// speedup vs baseline: 6.9454x; 1.0654x over previous
#include <cuda_runtime.h>

#define Bb 8
#define Tt 2048
#define Cc 1024
#define Hh 64
#define BT (Bb*Tt)

__device__ float g_q[BT*Hh];
__device__ float g_k[BT*Hh];
__device__ float g_v[BT*Hh];

__device__ __forceinline__ float fast_exp2(float x){
    float y;
    asm("ex2.approx.ftz.f32 %0, %1;" : "=f"(y) : "f"(x));
    return y;
}
__device__ __forceinline__ unsigned f2tf(float f){
    unsigned r;
    asm("cvt.rna.tf32.f32 %0, %1;" : "=r"(r) : "f"(f));
    return r;
}
__device__ __forceinline__ void mma_tf32(float c[4], const unsigned a[4], const unsigned b[2]){
    asm volatile("mma.sync.aligned.m16n8k8.row.col.f32.tf32.tf32.f32 "
        "{%0,%1,%2,%3}, {%4,%5,%6,%7}, {%8,%9}, {%0,%1,%2,%3};"
        : "+f"(c[0]), "+f"(c[1]), "+f"(c[2]), "+f"(c[3])
        : "r"(a[0]), "r"(a[1]), "r"(a[2]), "r"(a[3]), "r"(b[0]), "r"(b[1]));
}
__device__ __forceinline__ void cp16(unsigned dst, const void* src){
    asm volatile("cp.async.cg.shared.global [%0], [%1], 16;" :: "r"(dst), "l"(src));
}
__device__ __forceinline__ void cp_commit(){ asm volatile("cp.async.commit_group;"); }
__device__ __forceinline__ void cp_wait0(){ asm volatile("cp.async.wait_group 0;"); }

// ---------------------------------------------------------------------------
// Projection: out[BT x 64] = x[BT x 1024] @ W[1024 x 64]  (tf32 mma)
// 128x64 tile/block, 128 threads, cp.async double-buffered, cvt after LDS.
// ---------------------------------------------------------------------------
#define PROJ_XW 36            // x smem stride (words), 36 ≡ 4 (mod 32)
#define PROJ_WW 68            // W smem stride (words), 68 ≡ 4 (mod 32)
#define PROJ_XS (128*PROJ_XW) // 4608 words per stage
#define PROJ_WS (32*PROJ_WW)  // 2176 words per stage
#define PROJ_STAGE (PROJ_XS + PROJ_WS)
#define PROJ_SMEM (2*PROJ_STAGE*4)  // 54272 B

__global__ __launch_bounds__(128) void proj_kernel(
    const float* __restrict__ x,
    const float* __restrict__ Wk,
    const float* __restrict__ Wq,
    const float* __restrict__ Wv)
{
    const int m = blockIdx.y;
    const float* __restrict__ W = (m == 0) ? Wk : (m == 1) ? Wq : Wv;
    float* __restrict__ out = (m == 0) ? g_k : (m == 1) ? g_q : g_v;

    const int row0 = blockIdx.x * 128;
    const int tid  = threadIdx.x;
    const int warp = tid >> 5;
    const int lane = tid & 31;
    const int g = lane >> 2;
    const int t = lane & 3;

    extern __shared__ float sm[];
    const unsigned smb = (unsigned)__cvta_generic_to_shared(sm);

    float c[2][8][4];
#pragma unroll
    for (int mf = 0; mf < 2; mf++)
#pragma unroll
        for (int nf = 0; nf < 8; nf++)
#pragma unroll
            for (int i = 0; i < 4; i++) c[mf][nf][i] = 0.f;

    // per-thread load coordinates
    const int xr = tid >> 3, xc4 = (tid & 7) * 4;       // +16 rows per u
    const int wr = tid >> 4, wc4 = (tid & 15) * 4;      // +8 rows per u

    auto load_chunk = [&](int kc, int s){
        const unsigned xb = smb + (unsigned)(s * PROJ_STAGE) * 4u;
        const unsigned wb = xb + PROJ_XS * 4u;
#pragma unroll
        for (int u = 0; u < 8; u++) {
            int rr = xr + 16 * u;
            cp16(xb + (unsigned)(rr * PROJ_XW + xc4) * 4u,
                 &x[(size_t)(row0 + rr) * Cc + kc + xc4]);
        }
#pragma unroll
        for (int u = 0; u < 4; u++) {
            int rr = wr + 8 * u;
            cp16(wb + (unsigned)(rr * PROJ_WW + wc4) * 4u,
                 &W[(size_t)(kc + rr) * Hh + wc4]);
        }
        cp_commit();
    };

    load_chunk(0, 0);

    for (int it = 0; it < Cc / 32; it++) {
        cp_wait0();
        __syncthreads();
        if (it + 1 < Cc / 32) load_chunk((it + 1) * 32, (it + 1) & 1);

        const float* xs = sm + (it & 1) * PROJ_STAGE;
        const float* ws = xs + PROJ_XS;
#pragma unroll
        for (int ks = 0; ks < 4; ks++) {
            const int k0 = ks * 8;
            unsigned b[8][2];
#pragma unroll
            for (int nf = 0; nf < 8; nf++) {
                b[nf][0] = f2tf(ws[(k0 + t) * PROJ_WW + nf * 8 + g]);
                b[nf][1] = f2tf(ws[(k0 + t + 4) * PROJ_WW + nf * 8 + g]);
            }
#pragma unroll
            for (int mf = 0; mf < 2; mf++) {
                const int rg = warp * 32 + mf * 16 + g;
                unsigned a[4] = { f2tf(xs[rg * PROJ_XW + k0 + t]),
                                  f2tf(xs[(rg + 8) * PROJ_XW + k0 + t]),
                                  f2tf(xs[rg * PROJ_XW + k0 + t + 4]),
                                  f2tf(xs[(rg + 8) * PROJ_XW + k0 + t + 4]) };
#pragma unroll
                for (int nf = 0; nf < 8; nf++) mma_tf32(c[mf][nf], a, b[nf]);
            }
        }
        __syncthreads();
    }
#pragma unroll
    for (int mf = 0; mf < 2; mf++) {
        const int rg = row0 + warp * 32 + mf * 16 + g;
#pragma unroll
        for (int nf = 0; nf < 8; nf++) {
            const int col = nf * 8 + 2 * t;
            *(float2*)&out[(size_t)rg * Hh + col]       = make_float2(c[mf][nf][0], c[mf][nf][1]);
            *(float2*)&out[(size_t)(rg + 8) * Hh + col] = make_float2(c[mf][nf][2], c[mf][nf][3]);
        }
    }
}

// ---------------------------------------------------------------------------
// Flash attention, tf32 mma. 128 threads (4 warps), one 64-row q-tile/block.
// cp.async double-buffered K/V tiles, grid (32,8), heavy tiles first.
// ---------------------------------------------------------------------------
#define AW 68                  // K/V smem row stride (words), 68 ≡ 4 (mod 32)
#define ATILE (64*AW)          // one 64x64 tile, words
#define ASTAGE (2*ATILE)       // K + V
#define ATTN_SMEM (2*ASTAGE*4) // 69632 B

__global__ __launch_bounds__(128) void attn_kernel(float* __restrict__ out)
{
    const int b   = blockIdx.y;
    const int qt  = gridDim.x - 1 - blockIdx.x;   // heavy tiles first
    const int q0  = qt * 64;
    const int tid = threadIdx.x;
    const int warp = tid >> 5;
    const int lane = tid & 31;
    const int wr0 = warp * 16;
    const int g = lane >> 2;
    const int t = lane & 3;

    extern __shared__ float sm[];
    const unsigned smb = (unsigned)__cvta_generic_to_shared(sm);

    const float scale = 0.125f * 1.44269504088896340736f;  // 1/sqrt(64) * log2(e)

    // Q A-frags (scale folded, tf32), registers for whole kernel
    unsigned qa[8][4];
    {
        const float* qp = g_q + ((size_t)b * Tt + q0 + wr0) * Hh;
#pragma unroll
        for (int kc = 0; kc < 8; kc++) {
            qa[kc][0] = f2tf(qp[g * Hh + kc * 8 + t] * scale);
            qa[kc][1] = f2tf(qp[(g + 8) * Hh + kc * 8 + t] * scale);
            qa[kc][2] = f2tf(qp[g * Hh + kc * 8 + t + 4] * scale);
            qa[kc][3] = f2tf(qp[(g + 8) * Hh + kc * 8 + t + 4] * scale);
        }
    }

    float oc[8][4];
#pragma unroll
    for (int nf = 0; nf < 8; nf++)
#pragma unroll
        for (int i = 0; i < 4; i++) oc[nf][i] = 0.f;
    float m0 = -1e30f, m1 = -1e30f, l0 = 0.f, l1 = 0.f;

    const int src0 = (lane & ~3) | (t >> 1);
    const int src2 = src0 + 2;

    const int lrow = tid >> 4, lc4 = (tid & 15) * 4;   // tile load coords (+8 rows per u)

    auto load_tile = [&](int n0, int s){
        const unsigned kb = smb + (unsigned)(s * ASTAGE) * 4u;
        const unsigned vb = kb + ATILE * 4u;
        const float* kp = g_k + ((size_t)b * Tt + n0) * Hh;
        const float* vp = g_v + ((size_t)b * Tt + n0) * Hh;
#pragma unroll
        for (int u = 0; u < 8; u++) {
            int row = lrow + 8 * u;
            unsigned off = (unsigned)(row * AW + lc4) * 4u;
            cp16(kb + off, kp + (size_t)row * Hh + lc4);
            cp16(vb + off, vp + (size_t)row * Hh + lc4);
        }
        cp_commit();
    };

    const int nt = qt + 1;
    load_tile(0, 0);

    for (int it = 0; it < nt; it++) {
        cp_wait0();
        __syncthreads();
        if (it + 1 < nt) load_tile((it + 1) * 64, (it + 1) & 1);

        const float* Ks = sm + (it & 1) * ASTAGE;
        const float* Vs = Ks + ATILE;

        // S = Q K^T (log2 domain via folded scale)
        float sc_[8][4];
#pragma unroll
        for (int nf = 0; nf < 8; nf++)
#pragma unroll
            for (int i = 0; i < 4; i++) sc_[nf][i] = 0.f;
#pragma unroll
        for (int kc = 0; kc < 8; kc++) {
#pragma unroll
            for (int nf = 0; nf < 8; nf++) {
                unsigned bk[2] = { f2tf(Ks[(nf * 8 + g) * AW + kc * 8 + t]),
                                   f2tf(Ks[(nf * 8 + g) * AW + kc * 8 + t + 4]) };
                mma_tf32(sc_[nf], qa[kc], bk);
            }
        }

        if (it == nt - 1) {  // diagonal tile: causal mask
#pragma unroll
            for (int nf = 0; nf < 8; nf++) {
                const int kl = nf * 8 + 2 * t;
                if (kl     > wr0 + g)     sc_[nf][0] = -1e30f;
                if (kl + 1 > wr0 + g)     sc_[nf][1] = -1e30f;
                if (kl     > wr0 + g + 8) sc_[nf][2] = -1e30f;
                if (kl + 1 > wr0 + g + 8) sc_[nf][3] = -1e30f;
            }
        }

        // online softmax for rows g and g+8
        float mx0 = -1e30f, mx1 = -1e30f;
#pragma unroll
        for (int nf = 0; nf < 8; nf++) {
            mx0 = fmaxf(mx0, fmaxf(sc_[nf][0], sc_[nf][1]));
            mx1 = fmaxf(mx1, fmaxf(sc_[nf][2], sc_[nf][3]));
        }
        mx0 = fmaxf(mx0, __shfl_xor_sync(0xffffffffu, mx0, 1));
        mx0 = fmaxf(mx0, __shfl_xor_sync(0xffffffffu, mx0, 2));
        mx1 = fmaxf(mx1, __shfl_xor_sync(0xffffffffu, mx1, 1));
        mx1 = fmaxf(mx1, __shfl_xor_sync(0xffffffffu, mx1, 2));

        const float m0n = fmaxf(m0, mx0);
        const float m1n = fmaxf(m1, mx1);
        const float corr0 = fast_exp2(m0 - m0n);
        const float corr1 = fast_exp2(m1 - m1n);
        l0 *= corr0; l1 *= corr1;
#pragma unroll
        for (int nf = 0; nf < 8; nf++) {
            oc[nf][0] *= corr0; oc[nf][1] *= corr0;
            oc[nf][2] *= corr1; oc[nf][3] *= corr1;
        }
        unsigned pu[8][4];
#pragma unroll
        for (int nf = 0; nf < 8; nf++) {
            float p0 = fast_exp2(sc_[nf][0] - m0n);
            float p1 = fast_exp2(sc_[nf][1] - m0n);
            float p2 = fast_exp2(sc_[nf][2] - m1n);
            float p3 = fast_exp2(sc_[nf][3] - m1n);
            l0 += p0 + p1;
            l1 += p2 + p3;
            pu[nf][0] = f2tf(p0); pu[nf][1] = f2tf(p1);
            pu[nf][2] = f2tf(p2); pu[nf][3] = f2tf(p3);
        }
        m0 = m0n; m1 = m1n;

        // O += P V : P frag C->A re-layout via shuffles
#pragma unroll
        for (int kc = 0; kc < 8; kc++) {
            unsigned a[4];
            {
                unsigned e0 = __shfl_sync(0xffffffffu, pu[kc][0], src0);
                unsigned o0 = __shfl_sync(0xffffffffu, pu[kc][1], src0);
                a[0] = (t & 1) ? o0 : e0;
                unsigned e1 = __shfl_sync(0xffffffffu, pu[kc][2], src0);
                unsigned o1 = __shfl_sync(0xffffffffu, pu[kc][3], src0);
                a[1] = (t & 1) ? o1 : e1;
                unsigned e2 = __shfl_sync(0xffffffffu, pu[kc][0], src2);
                unsigned o2 = __shfl_sync(0xffffffffu, pu[kc][1], src2);
                a[2] = (t & 1) ? o2 : e2;
                unsigned e3 = __shfl_sync(0xffffffffu, pu[kc][2], src2);
                unsigned o3 = __shfl_sync(0xffffffffu, pu[kc][3], src2);
                a[3] = (t & 1) ? o3 : e3;
            }
#pragma unroll
            for (int nf = 0; nf < 8; nf++) {
                unsigned bv[2] = { f2tf(Vs[(kc * 8 + t) * AW + nf * 8 + g]),
                                   f2tf(Vs[(kc * 8 + t + 4) * AW + nf * 8 + g]) };
                mma_tf32(oc[nf], a, bv);
            }
        }
        __syncthreads();
    }

    l0 += __shfl_xor_sync(0xffffffffu, l0, 1);
    l0 += __shfl_xor_sync(0xffffffffu, l0, 2);
    l1 += __shfl_xor_sync(0xffffffffu, l1, 1);
    l1 += __shfl_xor_sync(0xffffffffu, l1, 2);
    const float inv0 = 1.0f / l0;
    const float inv1 = 1.0f / l1;

    const int rg = q0 + wr0 + g;
#pragma unroll
    for (int nf = 0; nf < 8; nf++) {
        const int col = nf * 8 + 2 * t;
        *(float2*)&out[((size_t)b * Tt + rg) * Hh + col] =
            make_float2(oc[nf][0] * inv0, oc[nf][1] * inv0);
        *(float2*)&out[((size_t)b * Tt + rg + 8) * Hh + col] =
            make_float2(oc[nf][2] * inv1, oc[nf][3] * inv1);
    }
}

extern "C" void kernel_launch(void* const* d_in, const int* in_sizes, int n_in,
                              void* d_out, int out_size)
{
    const float* x  = (const float*)d_in[0];
    const float* Wk = (const float*)d_in[1];
    const float* Wq = (const float*)d_in[2];
    const float* Wv = (const float*)d_in[3];
    float* out = (float*)d_out;

    cudaFuncSetAttribute(proj_kernel, cudaFuncAttributeMaxDynamicSharedMemorySize, PROJ_SMEM);
    cudaFuncSetAttribute(attn_kernel, cudaFuncAttributeMaxDynamicSharedMemorySize, ATTN_SMEM);

    dim3 pg(BT / 128, 3);
    proj_kernel<<<pg, 128, PROJ_SMEM>>>(x, Wk, Wq, Wv);

    dim3 ag(Tt / 64, Bb);
    attn_kernel<<<ag, 128, ATTN_SMEM>>>(out);
}

// round 5
// speedup vs baseline: 7.5988x; 1.0941x over previous
#include <cuda_runtime.h>

#define Bb 8
#define Tt 2048
#define Cc 1024
#define Hh 64
#define BT (Bb*Tt)

// q,k,v scratch, stored PRE-ROUNDED to tf32 bit patterns
__device__ float g_q[BT*Hh];
__device__ float g_k[BT*Hh];
__device__ float g_v[BT*Hh];

__device__ __forceinline__ float fast_exp2(float x){
    float y;
    asm("ex2.approx.ftz.f32 %0, %1;" : "=f"(y) : "f"(x));
    return y;
}
__device__ __forceinline__ unsigned f2tf(float f){
    unsigned r;
    asm("cvt.rna.tf32.f32 %0, %1;" : "=r"(r) : "f"(f));
    return r;
}
__device__ __forceinline__ void mma_tf32(float c[4], const unsigned a[4], const unsigned b[2]){
    asm volatile("mma.sync.aligned.m16n8k8.row.col.f32.tf32.tf32.f32 "
        "{%0,%1,%2,%3}, {%4,%5,%6,%7}, {%8,%9}, {%0,%1,%2,%3};"
        : "+f"(c[0]), "+f"(c[1]), "+f"(c[2]), "+f"(c[3])
        : "r"(a[0]), "r"(a[1]), "r"(a[2]), "r"(a[3]), "r"(b[0]), "r"(b[1]));
}
__device__ __forceinline__ void cp16(unsigned dst, const void* src){
    asm volatile("cp.async.cg.shared.global [%0], [%1], 16;" :: "r"(dst), "l"(src));
}
__device__ __forceinline__ void cp_commit(){ asm volatile("cp.async.commit_group;"); }
__device__ __forceinline__ void cp_wait0(){ asm volatile("cp.async.wait_group 0;"); }
__device__ __forceinline__ void bar_sync(int id){
    asm volatile("bar.sync %0, 128;" :: "r"(id));
}

// ---------------------------------------------------------------------------
// Projection: 256-row tile, 256 threads (8 warps x 32 rows), cp.async x,
// W via LDG+cvt+STS (pre-converted -> no b cvt in inner loop).
// Outputs pre-rounded to tf32.
// ---------------------------------------------------------------------------
#define PXW 36                 // x stride words
#define PWW 68                 // W stride words
#define PXS (256*PXW)          // 9216 words per x stage
#define PWS (32*PWW)           // 2176 words per W stage
#define PROJ_SMEM ((2*PXS + 2*PWS)*4)   // 91136 B

__global__ __launch_bounds__(256, 2) void proj_kernel(
    const float* __restrict__ x,
    const float* __restrict__ Wk,
    const float* __restrict__ Wq,
    const float* __restrict__ Wv)
{
    const int m = blockIdx.y;
    const float* __restrict__ W = (m == 0) ? Wk : (m == 1) ? Wq : Wv;
    float* __restrict__ out = (m == 0) ? g_k : (m == 1) ? g_q : g_v;

    const int row0 = blockIdx.x * 256;
    const int tid  = threadIdx.x;
    const int warp = tid >> 5;
    const int lane = tid & 31;
    const int g = lane >> 2;
    const int t = lane & 3;

    extern __shared__ float sm[];
    const unsigned smb = (unsigned)__cvta_generic_to_shared(sm);

    float c[2][8][4];
#pragma unroll
    for (int mf = 0; mf < 2; mf++)
#pragma unroll
        for (int nf = 0; nf < 8; nf++)
#pragma unroll
            for (int i = 0; i < 4; i++) c[mf][nf][i] = 0.f;

    const int xr = tid >> 3, xc4 = (tid & 7) * 4;   // +32 rows per u, 8 cp16/thread

    auto load_x = [&](int kc, int s){
#pragma unroll
        for (int u = 0; u < 8; u++) {
            int rr = xr + 32 * u;
            cp16(smb + (unsigned)(s * PXS + rr * PXW + xc4) * 4u,
                 &x[(size_t)(row0 + rr) * Cc + kc + xc4]);
        }
        cp_commit();
    };
    auto ldg_w = [&](int kc, float4 wv[2]){
#pragma unroll
        for (int u = 0; u < 2; u++) {
            int f = tid + 256 * u;
            wv[u] = *(const float4*)&W[(size_t)(kc + (f >> 4)) * Hh + (f & 15) * 4];
        }
    };
    auto sts_w = [&](int s, const float4 wv[2]){
        unsigned* wsm = (unsigned*)sm + 2 * PXS + s * PWS;
#pragma unroll
        for (int u = 0; u < 2; u++) {
            int f = tid + 256 * u;
            uint4 r = make_uint4(f2tf(wv[u].x), f2tf(wv[u].y), f2tf(wv[u].z), f2tf(wv[u].w));
            *(uint4*)&wsm[(f >> 4) * PWW + (f & 15) * 4] = r;
        }
    };

    float4 wv[2];
    load_x(0, 0);
    ldg_w(0, wv);
    sts_w(0, wv);

    for (int it = 0; it < Cc / 32; it++) {
        cp_wait0();
        __syncthreads();
        if (it + 1 < Cc / 32) {
            load_x((it + 1) * 32, (it + 1) & 1);
            ldg_w((it + 1) * 32, wv);          // LDG in flight over the compute
        }
        const float* xs = sm + (it & 1) * PXS;
        const unsigned* ws = (const unsigned*)sm + 2 * PXS + (it & 1) * PWS;
#pragma unroll
        for (int ks = 0; ks < 4; ks++) {
            const int k0 = ks * 8;
            unsigned b[8][2];
#pragma unroll
            for (int nf = 0; nf < 8; nf++) {
                b[nf][0] = ws[(k0 + t) * PWW + nf * 8 + g];
                b[nf][1] = ws[(k0 + t + 4) * PWW + nf * 8 + g];
            }
#pragma unroll
            for (int mf = 0; mf < 2; mf++) {
                const int rg = warp * 32 + mf * 16 + g;
                unsigned a[4] = { f2tf(xs[rg * PXW + k0 + t]),
                                  f2tf(xs[(rg + 8) * PXW + k0 + t]),
                                  f2tf(xs[rg * PXW + k0 + t + 4]),
                                  f2tf(xs[(rg + 8) * PXW + k0 + t + 4]) };
#pragma unroll
                for (int nf = 0; nf < 8; nf++) mma_tf32(c[mf][nf], a, b[nf]);
            }
        }
        if (it + 1 < Cc / 32) sts_w((it + 1) & 1, wv);
        __syncthreads();
    }
    // epilogue: pre-round to tf32 so attn can skip cvts
#pragma unroll
    for (int mf = 0; mf < 2; mf++) {
        const int rg = row0 + warp * 32 + mf * 16 + g;
#pragma unroll
        for (int nf = 0; nf < 8; nf++) {
            const int col = nf * 8 + 2 * t;
            *(float2*)&out[(size_t)rg * Hh + col] = make_float2(
                __uint_as_float(f2tf(c[mf][nf][0])), __uint_as_float(f2tf(c[mf][nf][1])));
            *(float2*)&out[(size_t)(rg + 8) * Hh + col] = make_float2(
                __uint_as_float(f2tf(c[mf][nf][2])), __uint_as_float(f2tf(c[mf][nf][3])));
        }
    }
}

// ---------------------------------------------------------------------------
// Flash attention: 256 threads = 2 groups x 4 warps. One 64-row q-tile/block.
// Group g processes key tiles of parity g (split-KV), own double-buffered smem,
// states merged at the end. No cvt in frag loads (inputs pre-rounded).
// ---------------------------------------------------------------------------
#define AW 68
#define ATILE (64*AW)          // 4352 words (one 64x64 tile)
#define ASTG (2*ATILE)         // K+V per (group,stage)
#define ATTN_SMEM (4*ASTG*4)   // 139264 B

__global__ __launch_bounds__(256, 1) void attn_kernel(float* __restrict__ out)
{
    const int b    = blockIdx.y;
    const int qt   = gridDim.x - 1 - blockIdx.x;   // heavy tiles first
    const int q0   = qt * 64;
    const int tid  = threadIdx.x;
    const int warp = tid >> 5;
    const int lane = tid & 31;
    const int group = warp >> 2;
    const int wl   = warp & 3;
    const int wr0  = wl * 16;
    const int g = lane >> 2;
    const int t = lane & 3;
    const int gtid = tid & 127;

    extern __shared__ float sm[];
    const unsigned smb = (unsigned)__cvta_generic_to_shared(sm);

    const float scale = 0.125f * 1.44269504088896340736f;  // 1/sqrt(64)*log2(e)

    unsigned qa[8][4];
    {
        const float* qp = g_q + ((size_t)b * Tt + q0 + wr0) * Hh;
#pragma unroll
        for (int kc = 0; kc < 8; kc++) {
            qa[kc][0] = f2tf(qp[g * Hh + kc * 8 + t] * scale);
            qa[kc][1] = f2tf(qp[(g + 8) * Hh + kc * 8 + t] * scale);
            qa[kc][2] = f2tf(qp[g * Hh + kc * 8 + t + 4] * scale);
            qa[kc][3] = f2tf(qp[(g + 8) * Hh + kc * 8 + t + 4] * scale);
        }
    }

    float oc[8][4];
#pragma unroll
    for (int nf = 0; nf < 8; nf++)
#pragma unroll
        for (int i = 0; i < 4; i++) oc[nf][i] = 0.f;
    float m0 = -1e30f, m1 = -1e30f, l0 = 0.f, l1 = 0.f;

    const int src0 = (lane & ~3) | (t >> 1);
    const int src2 = src0 + 2;
    const int lrow = gtid >> 4, lc4 = (gtid & 15) * 4;

    auto load_tile = [&](int n0, int s){
        const unsigned kb = smb + (unsigned)((group * 2 + s) * ASTG) * 4u;
        const float* kp = g_k + ((size_t)b * Tt + n0) * Hh;
        const float* vp = g_v + ((size_t)b * Tt + n0) * Hh;
#pragma unroll
        for (int u = 0; u < 8; u++) {
            int row = lrow + 8 * u;
            unsigned off = (unsigned)(row * AW + lc4) * 4u;
            cp16(kb + off, kp + (size_t)row * Hh + lc4);
            cp16(kb + ATILE * 4u + off, vp + (size_t)row * Hh + lc4);
        }
        cp_commit();
    };

    const int ntg = (qt >= group) ? ((qt - group) >> 1) + 1 : 0;
    if (ntg > 0) load_tile(group * 64, 0);

    for (int j = 0; j < ntg; j++) {
        cp_wait0();
        bar_sync(1 + group);
        if (j + 1 < ntg) load_tile((group + 2 * (j + 1)) * 64, (j + 1) & 1);

        const unsigned* Ks = (const unsigned*)sm + (group * 2 + (j & 1)) * ASTG;
        const unsigned* Vs = Ks + ATILE;

        // S = Q K^T (log2 domain)
        float sc_[8][4];
#pragma unroll
        for (int nf = 0; nf < 8; nf++)
#pragma unroll
            for (int i = 0; i < 4; i++) sc_[nf][i] = 0.f;
#pragma unroll
        for (int kc = 0; kc < 8; kc++) {
#pragma unroll
            for (int nf = 0; nf < 8; nf++) {
                unsigned bk[2] = { Ks[(nf * 8 + g) * AW + kc * 8 + t],
                                   Ks[(nf * 8 + g) * AW + kc * 8 + t + 4] };
                mma_tf32(sc_[nf], qa[kc], bk);
            }
        }

        if (group + 2 * j == qt) {  // diagonal tile
#pragma unroll
            for (int nf = 0; nf < 8; nf++) {
                const int kl = nf * 8 + 2 * t;
                if (kl     > wr0 + g)     sc_[nf][0] = -1e30f;
                if (kl + 1 > wr0 + g)     sc_[nf][1] = -1e30f;
                if (kl     > wr0 + g + 8) sc_[nf][2] = -1e30f;
                if (kl + 1 > wr0 + g + 8) sc_[nf][3] = -1e30f;
            }
        }

        float mx0 = -1e30f, mx1 = -1e30f;
#pragma unroll
        for (int nf = 0; nf < 8; nf++) {
            mx0 = fmaxf(mx0, fmaxf(sc_[nf][0], sc_[nf][1]));
            mx1 = fmaxf(mx1, fmaxf(sc_[nf][2], sc_[nf][3]));
        }
        mx0 = fmaxf(mx0, __shfl_xor_sync(0xffffffffu, mx0, 1));
        mx0 = fmaxf(mx0, __shfl_xor_sync(0xffffffffu, mx0, 2));
        mx1 = fmaxf(mx1, __shfl_xor_sync(0xffffffffu, mx1, 1));
        mx1 = fmaxf(mx1, __shfl_xor_sync(0xffffffffu, mx1, 2));

        const float m0n = fmaxf(m0, mx0);
        const float m1n = fmaxf(m1, mx1);
        const float corr0 = fast_exp2(m0 - m0n);
        const float corr1 = fast_exp2(m1 - m1n);
        l0 *= corr0; l1 *= corr1;
#pragma unroll
        for (int nf = 0; nf < 8; nf++) {
            oc[nf][0] *= corr0; oc[nf][1] *= corr0;
            oc[nf][2] *= corr1; oc[nf][3] *= corr1;
        }
        unsigned pu[8][4];
#pragma unroll
        for (int nf = 0; nf < 8; nf++) {
            float p0 = fast_exp2(sc_[nf][0] - m0n);
            float p1 = fast_exp2(sc_[nf][1] - m0n);
            float p2 = fast_exp2(sc_[nf][2] - m1n);
            float p3 = fast_exp2(sc_[nf][3] - m1n);
            l0 += p0 + p1;
            l1 += p2 + p3;
            pu[nf][0] = f2tf(p0); pu[nf][1] = f2tf(p1);
            pu[nf][2] = f2tf(p2); pu[nf][3] = f2tf(p3);
        }
        m0 = m0n; m1 = m1n;

#pragma unroll
        for (int kc = 0; kc < 8; kc++) {
            unsigned a[4];
            {
                unsigned e0 = __shfl_sync(0xffffffffu, pu[kc][0], src0);
                unsigned o0 = __shfl_sync(0xffffffffu, pu[kc][1], src0);
                a[0] = (t & 1) ? o0 : e0;
                unsigned e1 = __shfl_sync(0xffffffffu, pu[kc][2], src0);
                unsigned o1 = __shfl_sync(0xffffffffu, pu[kc][3], src0);
                a[1] = (t & 1) ? o1 : e1;
                unsigned e2 = __shfl_sync(0xffffffffu, pu[kc][0], src2);
                unsigned o2 = __shfl_sync(0xffffffffu, pu[kc][1], src2);
                a[2] = (t & 1) ? o2 : e2;
                unsigned e3 = __shfl_sync(0xffffffffu, pu[kc][2], src2);
                unsigned o3 = __shfl_sync(0xffffffffu, pu[kc][3], src2);
                a[3] = (t & 1) ? o3 : e3;
            }
#pragma unroll
            for (int nf = 0; nf < 8; nf++) {
                unsigned bv[2] = { Vs[(kc * 8 + t) * AW + nf * 8 + g],
                                   Vs[(kc * 8 + t + 4) * AW + nf * 8 + g] };
                mma_tf32(oc[nf], a, bv);
            }
        }
    }

    // ---- merge the two groups' partial softmax states ----
    __syncthreads();
    if (group == 1) {
        float* st = sm + (wl * 32 + lane) * 37;
#pragma unroll
        for (int nf = 0; nf < 8; nf++)
#pragma unroll
            for (int i = 0; i < 4; i++) st[nf * 4 + i] = oc[nf][i];
        st[32] = m0; st[33] = m1; st[34] = l0; st[35] = l1;
    }
    __syncthreads();
    if (group == 0) {
        const float* st = sm + (wl * 32 + lane) * 37;
        const float mb0 = st[32], mb1 = st[33], lb0 = st[34], lb1 = st[35];
        const float M0 = fmaxf(m0, mb0), M1 = fmaxf(m1, mb1);
        const float ca0 = fast_exp2(m0 - M0), cb0 = fast_exp2(mb0 - M0);
        const float ca1 = fast_exp2(m1 - M1), cb1 = fast_exp2(mb1 - M1);
        l0 = l0 * ca0 + lb0 * cb0;
        l1 = l1 * ca1 + lb1 * cb1;
#pragma unroll
        for (int nf = 0; nf < 8; nf++) {
            oc[nf][0] = oc[nf][0] * ca0 + st[nf * 4 + 0] * cb0;
            oc[nf][1] = oc[nf][1] * ca0 + st[nf * 4 + 1] * cb0;
            oc[nf][2] = oc[nf][2] * ca1 + st[nf * 4 + 2] * cb1;
            oc[nf][3] = oc[nf][3] * ca1 + st[nf * 4 + 3] * cb1;
        }

        l0 += __shfl_xor_sync(0xffffffffu, l0, 1);
        l0 += __shfl_xor_sync(0xffffffffu, l0, 2);
        l1 += __shfl_xor_sync(0xffffffffu, l1, 1);
        l1 += __shfl_xor_sync(0xffffffffu, l1, 2);
        const float inv0 = 1.0f / l0;
        const float inv1 = 1.0f / l1;

        const int rg = q0 + wr0 + g;
#pragma unroll
        for (int nf = 0; nf < 8; nf++) {
            const int col = nf * 8 + 2 * t;
            *(float2*)&out[((size_t)b * Tt + rg) * Hh + col] =
                make_float2(oc[nf][0] * inv0, oc[nf][1] * inv0);
            *(float2*)&out[((size_t)b * Tt + rg + 8) * Hh + col] =
                make_float2(oc[nf][2] * inv1, oc[nf][3] * inv1);
        }
    }
}

extern "C" void kernel_launch(void* const* d_in, const int* in_sizes, int n_in,
                              void* d_out, int out_size)
{
    const float* x  = (const float*)d_in[0];
    const float* Wk = (const float*)d_in[1];
    const float* Wq = (const float*)d_in[2];
    const float* Wv = (const float*)d_in[3];
    float* out = (float*)d_out;

    cudaFuncSetAttribute(proj_kernel, cudaFuncAttributeMaxDynamicSharedMemorySize, PROJ_SMEM);
    cudaFuncSetAttribute(attn_kernel, cudaFuncAttributeMaxDynamicSharedMemorySize, ATTN_SMEM);

    dim3 pg(BT / 256, 3);
    proj_kernel<<<pg, 256, PROJ_SMEM>>>(x, Wk, Wq, Wv);

    dim3 ag(Tt / 64, Bb);
    attn_kernel<<<ag, 256, ATTN_SMEM>>>(out);
}

// round 6
// speedup vs baseline: 9.0211x; 1.1872x over previous
#include <cuda_runtime.h>

#define Bb 8
#define Tt 2048
#define Cc 1024
#define Hh 64
#define BT (Bb*Tt)

// q,v scratch pre-rounded tf32; k additionally DIM-PERMUTED (pairs (t,t+4) adjacent)
__device__ float g_q[BT*Hh];
__device__ float g_k[BT*Hh];
__device__ float g_v[BT*Hh];
// split-KV partials
__device__ float g_pO[2*BT*Hh];
__device__ float g_pm[2*BT];
__device__ float g_pl[2*BT];

__device__ __forceinline__ float fast_exp2(float x){
    float y;
    asm("ex2.approx.ftz.f32 %0, %1;" : "=f"(y) : "f"(x));
    return y;
}
__device__ __forceinline__ unsigned f2tf(float f){
    unsigned r;
    asm("cvt.rna.tf32.f32 %0, %1;" : "=r"(r) : "f"(f));
    return r;
}
__device__ __forceinline__ void mma_tf32(float c[4], const unsigned a[4], const unsigned b[2]){
    asm volatile("mma.sync.aligned.m16n8k8.row.col.f32.tf32.tf32.f32 "
        "{%0,%1,%2,%3}, {%4,%5,%6,%7}, {%8,%9}, {%0,%1,%2,%3};"
        : "+f"(c[0]), "+f"(c[1]), "+f"(c[2]), "+f"(c[3])
        : "r"(a[0]), "r"(a[1]), "r"(a[2]), "r"(a[3]), "r"(b[0]), "r"(b[1]));
}
__device__ __forceinline__ void cp16(unsigned dst, const void* src){
    asm volatile("cp.async.cg.shared.global [%0], [%1], 16;" :: "r"(dst), "l"(src));
}
__device__ __forceinline__ void cp_commit(){ asm volatile("cp.async.commit_group;"); }
__device__ __forceinline__ void cp_wait0(){ asm volatile("cp.async.wait_group 0;"); }
__device__ __forceinline__ void cp_wait1(){ asm volatile("cp.async.wait_group 1;"); }
__device__ __forceinline__ void bar_sync(int id){
    asm volatile("bar.sync %0, 128;" :: "r"(id));
}

// ---------------------------------------------------------------------------
// Fused projection: [BT x 1024] @ [1024 x 192] (Wk|Wq|Wv). x read ONCE.
// 64x192 tile/block, 256 threads = 8 warps (2 m x 4 n), warp tile 32x48.
// Outputs pre-rounded tf32; k output dim-permuted for attn LDS.64.
// ---------------------------------------------------------------------------
#define PXW 36                 // x stride words (==4 mod 32)
#define PWW 200                // W stride words (==8 mod 32)
#define PXS (64*PXW)           // 2304
#define PWS (32*PWW)           // 6400
#define PROJ_SMEM ((2*PXS + 2*PWS)*4)   // 69632 B

__global__ __launch_bounds__(256, 2) void proj_kernel(
    const float* __restrict__ x,
    const float* __restrict__ Wk,
    const float* __restrict__ Wq,
    const float* __restrict__ Wv)
{
    const int row0 = blockIdx.x * 64;
    const int tid  = threadIdx.x;
    const int warp = tid >> 5;
    const int lane = tid & 31;
    const int mw = warp >> 2;      // 0..1
    const int wn = warp & 3;       // 0..3
    const int g = lane >> 2;
    const int t = lane & 3;

    extern __shared__ float sm[];
    const unsigned smb = (unsigned)__cvta_generic_to_shared(sm);

    float c[2][6][4];
#pragma unroll
    for (int mf = 0; mf < 2; mf++)
#pragma unroll
        for (int nf = 0; nf < 6; nf++)
#pragma unroll
            for (int i = 0; i < 4; i++) c[mf][nf][i] = 0.f;

    auto load_x = [&](int kc, int s){
#pragma unroll
        for (int u = 0; u < 2; u++) {
            int f = tid + 256 * u;           // 512 float4
            int rr = f >> 3, c4 = (f & 7) * 4;
            cp16(smb + (unsigned)(s * PXS + rr * PXW + c4) * 4u,
                 &x[(size_t)(row0 + rr) * Cc + kc + c4]);
        }
        cp_commit();
    };
    auto ldg_w = [&](int kc, float4 wv[6]){
#pragma unroll
        for (int u = 0; u < 6; u++) {
            int f = tid + 256 * u;           // 1536 float4, 48 per row
            int rr = f / 48, cc = (f % 48) * 4;
            const float* src = (cc < 64) ? &Wk[(size_t)(kc + rr) * Hh + cc]
                             : (cc < 128) ? &Wq[(size_t)(kc + rr) * Hh + cc - 64]
                                          : &Wv[(size_t)(kc + rr) * Hh + cc - 128];
            wv[u] = *(const float4*)src;
        }
    };
    auto sts_w = [&](int s, const float4 wv[6]){
        unsigned* wsm = (unsigned*)sm + 2 * PXS + s * PWS;
#pragma unroll
        for (int u = 0; u < 6; u++) {
            int f = tid + 256 * u;
            int rr = f / 48, cc = (f % 48) * 4;
            *(uint4*)&wsm[rr * PWW + cc] =
                make_uint4(f2tf(wv[u].x), f2tf(wv[u].y), f2tf(wv[u].z), f2tf(wv[u].w));
        }
    };

    float4 wv[6];
    load_x(0, 0);
    ldg_w(0, wv);
    sts_w(0, wv);

    for (int it = 0; it < Cc / 32; it++) {
        cp_wait0();
        __syncthreads();
        if (it + 1 < Cc / 32) {
            load_x((it + 1) * 32, (it + 1) & 1);
            ldg_w((it + 1) * 32, wv);
        }
        const float* xs = sm + (it & 1) * PXS;
        const unsigned* ws = (const unsigned*)sm + 2 * PXS + (it & 1) * PWS;
#pragma unroll
        for (int ks = 0; ks < 4; ks++) {
            const int k0 = ks * 8;
            unsigned b[6][2];
#pragma unroll
            for (int nf = 0; nf < 6; nf++) {
                b[nf][0] = ws[(k0 + t) * PWW + wn * 48 + nf * 8 + g];
                b[nf][1] = ws[(k0 + t + 4) * PWW + wn * 48 + nf * 8 + g];
            }
#pragma unroll
            for (int mf = 0; mf < 2; mf++) {
                const int rg = mw * 32 + mf * 16 + g;
                unsigned a[4] = { f2tf(xs[rg * PXW + k0 + t]),
                                  f2tf(xs[(rg + 8) * PXW + k0 + t]),
                                  f2tf(xs[rg * PXW + k0 + t + 4]),
                                  f2tf(xs[(rg + 8) * PXW + k0 + t + 4]) };
#pragma unroll
                for (int nf = 0; nf < 6; nf++) mma_tf32(c[mf][nf], a, b[nf]);
            }
        }
        if (it + 1 < Cc / 32) sts_w((it + 1) & 1, wv);
        __syncthreads();
    }

    // epilogue: pre-round tf32; k gets dim permutation p(o)=2*(o&3)+(o>>2)
#pragma unroll
    for (int mf = 0; mf < 2; mf++) {
        const size_t r0 = row0 + mw * 32 + mf * 16 + g;
#pragma unroll
        for (int nf = 0; nf < 6; nf++) {
            const int col = wn * 48 + nf * 8 + 2 * t;
            float v0 = __uint_as_float(f2tf(c[mf][nf][0]));
            float v1 = __uint_as_float(f2tf(c[mf][nf][1]));
            float v2 = __uint_as_float(f2tf(c[mf][nf][2]));
            float v3 = __uint_as_float(f2tf(c[mf][nf][3]));
            if (col < 64) {            // k: permuted scatter
                const int base = col & ~7, o = col & 7;
                const int p0 = base + 2 * (o & 3) + (o >> 2);
                const int p1 = base + 2 * ((o + 1) & 3) + ((o + 1) >> 2);
                g_k[r0 * Hh + p0] = v0;       g_k[r0 * Hh + p1] = v1;
                g_k[(r0 + 8) * Hh + p0] = v2; g_k[(r0 + 8) * Hh + p1] = v3;
            } else {
                float* po = (col < 128) ? g_q : g_v;
                const int l = (col < 128) ? col - 64 : col - 128;
                *(float2*)&po[r0 * Hh + l]       = make_float2(v0, v1);
                *(float2*)&po[(r0 + 8) * Hh + l] = make_float2(v2, v3);
            }
        }
    }
}

// ---------------------------------------------------------------------------
// Flash attention, split-KV x2 at block level + dual group split in block.
// grid (32, 2, 8), 256 threads. Single-stage smem, staged K/V cp.async.
// Writes unnormalized partials (O', m, l); merge_kernel finalizes.
// ---------------------------------------------------------------------------
#define AW 72                  // K and V stride words (==8 mod 32)
#define ATILE (64*AW)          // 4608 words
#define ATTN_SMEM (4*ATILE*4)  // 73728 B  (2 groups x (K,V))

__global__ __launch_bounds__(256, 2) void attn_kernel()
{
    const int qt   = (int)gridDim.x - 1 - (int)blockIdx.x;   // heavy first
    const int half = blockIdx.y;
    const int b    = blockIdx.z;
    const int q0   = qt * 64;
    const int tid  = threadIdx.x;
    const int warp = tid >> 5;
    const int lane = tid & 31;
    const int group = warp >> 2;
    const int wl   = warp & 3;
    const int wr0  = wl * 16;
    const int g = lane >> 2;
    const int t = lane & 3;
    const int gtid = tid & 127;

    extern __shared__ float sm[];
    const unsigned smb = (unsigned)__cvta_generic_to_shared(sm);

    const float scale = 0.125f * 1.44269504088896340736f;

    unsigned qa[8][4];
    {
        const float* qp = g_q + ((size_t)b * Tt + q0 + wr0) * Hh;
#pragma unroll
        for (int kc = 0; kc < 8; kc++) {
            qa[kc][0] = f2tf(qp[g * Hh + kc * 8 + t] * scale);
            qa[kc][1] = f2tf(qp[(g + 8) * Hh + kc * 8 + t] * scale);
            qa[kc][2] = f2tf(qp[g * Hh + kc * 8 + t + 4] * scale);
            qa[kc][3] = f2tf(qp[(g + 8) * Hh + kc * 8 + t + 4] * scale);
        }
    }

    float oc[8][4];
#pragma unroll
    for (int nf = 0; nf < 8; nf++)
#pragma unroll
        for (int i = 0; i < 4; i++) oc[nf][i] = 0.f;
    float m0 = -1e30f, m1 = -1e30f, l0 = 0.f, l1 = 0.f;

    const int src0 = (lane & ~3) | (t >> 1);
    const int src2 = src0 + 2;
    const int lrow = gtid >> 4, lc4 = (gtid & 15) * 4;

    const unsigned kb = smb + (unsigned)(group * 2 * ATILE) * 4u;
    const unsigned vb = kb + ATILE * 4u;

    auto load_k = [&](int n0){
        const float* kp = g_k + ((size_t)b * Tt + n0) * Hh;
#pragma unroll
        for (int u = 0; u < 8; u++) {
            int row = lrow + 8 * u;
            cp16(kb + (unsigned)(row * AW + lc4) * 4u, kp + (size_t)row * Hh + lc4);
        }
        cp_commit();
    };
    auto load_v = [&](int n0){
        const float* vp = g_v + ((size_t)b * Tt + n0) * Hh;
#pragma unroll
        for (int u = 0; u < 8; u++) {
            int row = lrow + 8 * u;
            cp16(vb + (unsigned)(row * AW + lc4) * 4u, vp + (size_t)row * Hh + lc4);
        }
        cp_commit();
    };

    const int nt = qt + 1;
    const int s  = (half == 0) ? 0 : (nt + 1) / 2;
    const int e  = (half == 0) ? (nt + 1) / 2 : nt;
    const int ng = (e - s > group) ? ((e - s - group + 1) >> 1) : 0;

    if (ng > 0) { load_k((s + group) * 64); load_v((s + group) * 64); }

    const unsigned* Ks = (const unsigned*)sm + group * 2 * ATILE;
    const unsigned* Vs = Ks + ATILE;

    for (int j = 0; j < ng; j++) {
        const int tile = s + 2 * j + group;

        cp_wait1();               // own K chunks ready
        bar_sync(1 + group);      // everyone's K ready / prev Vs consumers done

        float sc[8][4];
#pragma unroll
        for (int nf = 0; nf < 8; nf++)
#pragma unroll
            for (int i = 0; i < 4; i++) sc[nf][i] = 0.f;
#pragma unroll
        for (int kc = 0; kc < 8; kc++) {
#pragma unroll
            for (int nf = 0; nf < 8; nf++) {
                uint2 kk = *(const uint2*)&Ks[(nf * 8 + g) * AW + kc * 8 + 2 * t];
                unsigned bk[2] = { kk.x, kk.y };
                mma_tf32(sc[nf], qa[kc], bk);
            }
        }
        bar_sync(1 + group);      // Ks consumed
        if (j + 1 < ng) load_k((tile + 2) * 64);

        if (tile == qt) {
#pragma unroll
            for (int nf = 0; nf < 8; nf++) {
                const int kl = nf * 8 + 2 * t;
                if (kl     > wr0 + g)     sc[nf][0] = -1e30f;
                if (kl + 1 > wr0 + g)     sc[nf][1] = -1e30f;
                if (kl     > wr0 + g + 8) sc[nf][2] = -1e30f;
                if (kl + 1 > wr0 + g + 8) sc[nf][3] = -1e30f;
            }
        }

        float mx0 = -1e30f, mx1 = -1e30f;
#pragma unroll
        for (int nf = 0; nf < 8; nf++) {
            mx0 = fmaxf(mx0, fmaxf(sc[nf][0], sc[nf][1]));
            mx1 = fmaxf(mx1, fmaxf(sc[nf][2], sc[nf][3]));
        }
        mx0 = fmaxf(mx0, __shfl_xor_sync(0xffffffffu, mx0, 1));
        mx0 = fmaxf(mx0, __shfl_xor_sync(0xffffffffu, mx0, 2));
        mx1 = fmaxf(mx1, __shfl_xor_sync(0xffffffffu, mx1, 1));
        mx1 = fmaxf(mx1, __shfl_xor_sync(0xffffffffu, mx1, 2));

        const float m0n = fmaxf(m0, mx0);
        const float m1n = fmaxf(m1, mx1);
        const float corr0 = fast_exp2(m0 - m0n);
        const float corr1 = fast_exp2(m1 - m1n);
        l0 *= corr0; l1 *= corr1;
#pragma unroll
        for (int nf = 0; nf < 8; nf++) {
            oc[nf][0] *= corr0; oc[nf][1] *= corr0;
            oc[nf][2] *= corr1; oc[nf][3] *= corr1;
        }
        // exp + convert in place (sc now holds tf32 bit patterns of P)
#pragma unroll
        for (int nf = 0; nf < 8; nf++) {
            float p0 = fast_exp2(sc[nf][0] - m0n);
            float p1 = fast_exp2(sc[nf][1] - m0n);
            float p2 = fast_exp2(sc[nf][2] - m1n);
            float p3 = fast_exp2(sc[nf][3] - m1n);
            l0 += p0 + p1;
            l1 += p2 + p3;
            sc[nf][0] = __uint_as_float(f2tf(p0));
            sc[nf][1] = __uint_as_float(f2tf(p1));
            sc[nf][2] = __uint_as_float(f2tf(p2));
            sc[nf][3] = __uint_as_float(f2tf(p3));
        }
        m0 = m0n; m1 = m1n;

        cp_wait1();               // own V chunks ready
        bar_sync(1 + group);      // everyone's V ready

#pragma unroll
        for (int kc = 0; kc < 8; kc++) {
            unsigned a[4];
            {
                unsigned p0 = __float_as_uint(sc[kc][0]);
                unsigned p1 = __float_as_uint(sc[kc][1]);
                unsigned p2 = __float_as_uint(sc[kc][2]);
                unsigned p3 = __float_as_uint(sc[kc][3]);
                unsigned e0 = __shfl_sync(0xffffffffu, p0, src0);
                unsigned o0 = __shfl_sync(0xffffffffu, p1, src0);
                a[0] = (t & 1) ? o0 : e0;
                unsigned e1 = __shfl_sync(0xffffffffu, p2, src0);
                unsigned o1 = __shfl_sync(0xffffffffu, p3, src0);
                a[1] = (t & 1) ? o1 : e1;
                unsigned e2 = __shfl_sync(0xffffffffu, p0, src2);
                unsigned o2 = __shfl_sync(0xffffffffu, p1, src2);
                a[2] = (t & 1) ? o2 : e2;
                unsigned e3 = __shfl_sync(0xffffffffu, p2, src2);
                unsigned o3 = __shfl_sync(0xffffffffu, p3, src2);
                a[3] = (t & 1) ? o3 : e3;
            }
#pragma unroll
            for (int nf = 0; nf < 8; nf++) {
                unsigned bv[2] = { Vs[(kc * 8 + t) * AW + nf * 8 + g],
                                   Vs[(kc * 8 + t + 4) * AW + nf * 8 + g] };
                mma_tf32(oc[nf], a, bv);
            }
        }
        bar_sync(1 + group);      // Vs consumed
        if (j + 1 < ng) load_v((tile + 2) * 64);
    }

    // ---- merge group partials, write block partial (unnormalized) ----
    __syncthreads();
    if (group == 1) {
        float* st = sm + (wl * 32 + lane) * 37;
#pragma unroll
        for (int nf = 0; nf < 8; nf++)
#pragma unroll
            for (int i = 0; i < 4; i++) st[nf * 4 + i] = oc[nf][i];
        st[32] = m0; st[33] = m1; st[34] = l0; st[35] = l1;
    }
    __syncthreads();
    if (group == 0) {
        const float* st = sm + (wl * 32 + lane) * 37;
        const float mb0 = st[32], mb1 = st[33], lb0 = st[34], lb1 = st[35];
        const float M0 = fmaxf(m0, mb0), M1 = fmaxf(m1, mb1);
        const float ca0 = fast_exp2(m0 - M0), cb0 = fast_exp2(mb0 - M0);
        const float ca1 = fast_exp2(m1 - M1), cb1 = fast_exp2(mb1 - M1);
        l0 = l0 * ca0 + lb0 * cb0;
        l1 = l1 * ca1 + lb1 * cb1;
#pragma unroll
        for (int nf = 0; nf < 8; nf++) {
            oc[nf][0] = oc[nf][0] * ca0 + st[nf * 4 + 0] * cb0;
            oc[nf][1] = oc[nf][1] * ca0 + st[nf * 4 + 1] * cb0;
            oc[nf][2] = oc[nf][2] * ca1 + st[nf * 4 + 2] * cb1;
            oc[nf][3] = oc[nf][3] * ca1 + st[nf * 4 + 3] * cb1;
        }
        l0 += __shfl_xor_sync(0xffffffffu, l0, 1);
        l0 += __shfl_xor_sync(0xffffffffu, l0, 2);
        l1 += __shfl_xor_sync(0xffffffffu, l1, 1);
        l1 += __shfl_xor_sync(0xffffffffu, l1, 2);

        const size_t row = (size_t)b * Tt + q0 + wr0 + g;
        float* po = g_pO + ((size_t)half * BT + row) * Hh;
#pragma unroll
        for (int nf = 0; nf < 8; nf++) {
            const int col = nf * 8 + 2 * t;
            *(float2*)&po[col]            = make_float2(oc[nf][0], oc[nf][1]);
            *(float2*)&po[8 * Hh + col]   = make_float2(oc[nf][2], oc[nf][3]);
        }
        if (t == 0) {
            g_pm[half * BT + row] = fmaxf(M0, m0);      // M0 (post-merge max)
            g_pl[half * BT + row] = l0;
            g_pm[half * BT + row + 8] = fmaxf(M1, m1);
            g_pl[half * BT + row + 8] = l1;
        }
    }
}

// ---------------------------------------------------------------------------
// Merge the two KV halves and normalize.
// ---------------------------------------------------------------------------
__global__ __launch_bounds__(128) void merge_kernel(float* __restrict__ out)
{
    const int row = blockIdx.x * 128 + threadIdx.x;
    const float ma = g_pm[row],      mb = g_pm[BT + row];
    const float la = g_pl[row],      lb = g_pl[BT + row];
    const float M  = fmaxf(ma, mb);
    float ca = fast_exp2(ma - M);
    float cb = fast_exp2(mb - M);
    const float inv = 1.0f / (la * ca + lb * cb);
    ca *= inv; cb *= inv;
    const float4* oa = (const float4*)&g_pO[(size_t)row * Hh];
    const float4* ob = (const float4*)&g_pO[(size_t)(BT + row) * Hh];
    float4* po = (float4*)&out[(size_t)row * Hh];
#pragma unroll
    for (int d4 = 0; d4 < 16; d4++) {
        float4 va = oa[d4], vb = ob[d4];
        po[d4] = make_float4(va.x * ca + vb.x * cb, va.y * ca + vb.y * cb,
                             va.z * ca + vb.z * cb, va.w * ca + vb.w * cb);
    }
}

extern "C" void kernel_launch(void* const* d_in, const int* in_sizes, int n_in,
                              void* d_out, int out_size)
{
    const float* x  = (const float*)d_in[0];
    const float* Wk = (const float*)d_in[1];
    const float* Wq = (const float*)d_in[2];
    const float* Wv = (const float*)d_in[3];
    float* out = (float*)d_out;

    cudaFuncSetAttribute(proj_kernel, cudaFuncAttributeMaxDynamicSharedMemorySize, PROJ_SMEM);
    cudaFuncSetAttribute(attn_kernel, cudaFuncAttributeMaxDynamicSharedMemorySize, ATTN_SMEM);

    proj_kernel<<<BT / 64, 256, PROJ_SMEM>>>(x, Wk, Wq, Wv);

    dim3 ag(Tt / 64, 2, Bb);
    attn_kernel<<<ag, 256, ATTN_SMEM>>>();

    merge_kernel<<<BT / 128, 128>>>(out);
}